// round 11
// baseline (speedup 1.0000x reference)
#include <cuda_runtime.h>
#include <stdint.h>

#define BB 32
#define AA 65536
#define CC 21
#define NANCH (BB*AA)
#define TILE 128
#define NTHR 128
#define MAIN_BLOCKS (NANCH/TILE)   // 16384
#define PADW 32                    // pad hot counters to separate cache lines

// ---------------- scratch (device globals; no allocation allowed) ----------
__device__ float        g_cand[NANCH];        // compacted nonzero neg CEs per row
__device__ unsigned int g_cnt[BB*PADW];       // per-row nonzero count
__device__ int          g_numpos[BB*PADW];    // per-row positive count
__device__ double       g_rowneg[BB];         // per-row total nonzero-neg sum
__device__ double       g_locsum;             // global smooth-L1 sum
__device__ double       g_posce;              // global positive-CE sum

// ---------------- helpers ---------------------------------------------------
// Reduce four doubles across an NTHR-thread block. Results valid on tid 0.
__device__ __forceinline__ void blockReduce4(double& x, double& y, double& z, double& w,
                                             double* sred /* >= NTHR/32*4 doubles */) {
    int lane = threadIdx.x & 31, wid = threadIdx.x >> 5;
#pragma unroll
    for (int o = 16; o; o >>= 1) {
        x += __shfl_down_sync(0xffffffffu, x, o);
        y += __shfl_down_sync(0xffffffffu, y, o);
        z += __shfl_down_sync(0xffffffffu, z, o);
        w += __shfl_down_sync(0xffffffffu, w, o);
    }
    if (lane == 0) {
        sred[wid*4]   = x; sred[wid*4+1] = y;
        sred[wid*4+2] = z; sred[wid*4+3] = w;
    }
    __syncthreads();
    if (wid == 0) {
        const int NW = NTHR/32;
        double a = (lane < NW) ? sred[lane*4]   : 0.0;
        double b = (lane < NW) ? sred[lane*4+1] : 0.0;
        double c = (lane < NW) ? sred[lane*4+2] : 0.0;
        double d = (lane < NW) ? sred[lane*4+3] : 0.0;
#pragma unroll
        for (int o = 2; o; o >>= 1) {          // NW=4 -> offsets 2,1
            a += __shfl_down_sync(0xffffffffu, a, o);
            b += __shfl_down_sync(0xffffffffu, b, o);
            c += __shfl_down_sync(0xffffffffu, c, o);
            d += __shfl_down_sync(0xffffffffu, d, o);
        }
        x = a; y = b; z = c; w = d;
    }
}

struct DigitSmem {
    unsigned sS[256];
    unsigned sc[256];
    unsigned swm[8];
    unsigned sdig;
};

// Block-parallel (256 threads) digit finder over a 256-bin shared histogram.
__device__ __forceinline__ unsigned find_digit(const unsigned* __restrict__ hist,
                                               long long& krem, DigitSmem* ds) {
    const int tid = threadIdx.x, lane = tid & 31, w = tid >> 5;
    unsigned c = hist[tid];
    unsigned S = c;
#pragma unroll
    for (int off = 1; off < 32; off <<= 1) {
        unsigned t = __shfl_down_sync(0xffffffffu, S, off);
        if (lane + off < 32) S += t;
    }
    if (lane == 0) ds->swm[w] = S;
    __syncthreads();
    unsigned add = 0;
#pragma unroll
    for (int ww = 0; ww < 8; ww++) if (ww > w) add += ds->swm[ww];
    S += add;
    ds->sS[tid] = S;
    ds->sc[tid] = c;
    __syncthreads();
    bool p = ((long long)S >= krem);
    unsigned bal = __ballot_sync(0xffffffffu, p);
    __syncthreads();
    if (lane == 0) ds->swm[w] = bal;
    __syncthreads();
    if (tid == 0) {
        int dig = 0;
#pragma unroll
        for (int ww = 7; ww >= 0; --ww) {
            if (ds->swm[ww]) { dig = ww * 32 + (31 - __clz(ds->swm[ww])); break; }
        }
        ds->sdig = (unsigned)dig;
    }
    __syncthreads();
    unsigned d = ds->sdig;
    krem -= (long long)ds->sS[d] - (long long)ds->sc[d];
    return d;
}

// ---------------- main kernel: 128 anchors per 128-thread block ---------------
__global__ void __launch_bounds__(NTHR) main_k(const float* __restrict__ locp,
                                               const float* __restrict__ loct,
                                               const float* __restrict__ cls,
                                               const int* __restrict__ tgt) {
    __shared__ float  scls[TILE*CC];   // 10752 B
    __shared__ double sred[(NTHR/32)*4];

    const int tid    = threadIdx.x;
    const int lane   = tid & 31;
    const int anchor = blockIdx.x * TILE + tid;
    const int row    = anchor >> 16;   // uniform per block (512 tiles per row)

    // ---- stage cls tile (coalesced float4, streaming, store immediately) ----
    {
        const float4* src = reinterpret_cast<const float4*>(cls) + (size_t)blockIdx.x * (TILE*CC/4);
        float4*       dst = reinterpret_cast<float4*>(scls);
#pragma unroll
        for (int i = 0; i < 6; i++) {
            int idx = tid + i * NTHR;
            if (idx < TILE*CC/4) dst[idx] = __ldcs(&src[idx]);
        }
    }
    __syncthreads();

    int  t   = tgt[anchor];
    bool pos = (t > 0);

    // ---- logsumexp over 21 classes (stride-21 LDS is bank-conflict-free) ----
    float v[CC];
#pragma unroll
    for (int c = 0; c < CC; c++) v[c] = scls[tid*CC + c];
    float m = v[0];
#pragma unroll
    for (int c = 1; c < CC; c++) m = fmaxf(m, v[c]);
    float s = 0.f;
#pragma unroll
    for (int c = 0; c < CC; c++) s += __expf(v[c] - m);

    int tc = t; tc = tc < 0 ? 0 : (tc > CC-1 ? CC-1 : tc);
    float picked = scls[tid*CC + tc];
    float ce     = (t == -1) ? 0.f : (m + __logf(s) - picked);
    float negc   = pos ? 0.f : ce;

    // ---- compact nonzero negatives (warp-aggregated) ----
    {
        unsigned bits = __float_as_uint(negc);
        unsigned mkz  = __ballot_sync(0xffffffffu, bits != 0u);
        if (mkz) {
            int leader = __ffs(mkz) - 1;
            unsigned base = 0;
            if (lane == leader) base = atomicAdd(&g_cnt[row*PADW], (unsigned)__popc(mkz));
            base = __shfl_sync(0xffffffffu, base, leader);
            if (bits != 0u) {
                unsigned off = (unsigned)__popc(mkz & ((1u << lane) - 1u));
                g_cand[(size_t)row*AA + base + off] = negc;
            }
        }
    }

    // ---- smooth-L1 (streaming loads; masked result) ----
    float4 p = __ldcs(&reinterpret_cast<const float4*>(locp)[anchor]);
    float4 q = __ldcs(&reinterpret_cast<const float4*>(loct)[anchor]);
    float d0 = p.x-q.x, d1 = p.y-q.y, d2 = p.z-q.z, d3 = p.w-q.w;
    float a0 = fabsf(d0), a1 = fabsf(d1), a2 = fabsf(d2), a3 = fabsf(d3);
    float lsum = (a0 < 1.f ? 0.5f*d0*d0 : a0-0.5f)
               + (a1 < 1.f ? 0.5f*d1*d1 : a1-0.5f)
               + (a2 < 1.f ? 0.5f*d2*d2 : a2-0.5f)
               + (a3 < 1.f ? 0.5f*d3*d3 : a3-0.5f);

    double bl = pos ? (double)lsum : 0.0;
    double bp = pos ? (double)ce   : 0.0;
    double bn = (double)negc;
    double bc = pos ? 1.0 : 0.0;
    blockReduce4(bl, bp, bn, bc, sred);

    if (tid == 0) {
        atomicAdd(&g_locsum, bl);
        atomicAdd(&g_posce,  bp);
        atomicAdd(&g_rowneg[row], bn);
        atomicAdd(&g_numpos[row*PADW], (int)bc);
    }
}

// ---------------- single-block select + combine + reset -----------------------
__global__ void __launch_bounds__(256) select_k(float* __restrict__ out) {
    __shared__ DigitSmem ds;
    __shared__ unsigned  shist[256];
    __shared__ double    sred[32];
    __shared__ double    s_negrow[BB];
    __shared__ long long s_k[BB];
    __shared__ int       s_n[BB];
    __shared__ int       s_slow[BB];
    __shared__ int       s_nslow;

    const int tid = threadIdx.x;

    if (tid == 0) s_nslow = 0;
    __syncthreads();

    // fast path per row (lane-parallel): k >= n  ->  negrow = total nonzero sum
    if (tid < BB) {
        int row  = tid;
        int n    = (int)g_cnt[row*PADW];
        int npos = g_numpos[row*PADW];
        long long k = 3LL * (long long)npos;
        if (k < 1) k = 1;
        if (k > AA-1) k = AA-1;
        s_n[row] = n;
        s_k[row] = k;
        if (k >= (long long)n) {
            s_negrow[row] = g_rowneg[row];
        } else {
            int slot = atomicAdd(&s_nslow, 1);
            s_slow[slot] = row;
        }
    }
    __syncthreads();

    // slow path (block-sequential per offending row; exercised only when k < n)
    for (int si = 0; si < s_nslow; si++) {
        const int row = s_slow[si];
        const int n   = s_n[row];
        long long krem = s_k[row];
        const float* cand = g_cand + (size_t)row*AA;

        shist[tid] = 0u;
        __syncthreads();
        for (int i = tid; i < n; i += 256)
            atomicAdd(&shist[__float_as_uint(cand[i]) >> 24], 1u);
        __syncthreads();
        unsigned pfx = find_digit(shist, krem, &ds);
#pragma unroll
        for (int shift = 16; shift >= 0; shift -= 8) {
            __syncthreads();
            shist[tid] = 0u;
            __syncthreads();
            for (int i = tid; i < n; i += 256) {
                unsigned b = __float_as_uint(cand[i]);
                if ((b >> (shift + 8)) == pfx)
                    atomicAdd(&shist[(b >> shift) & 255u], 1u);
            }
            __syncthreads();
            pfx = (pfx << 8) | find_digit(shist, krem, &ds);
        }
        const unsigned tb = pfx;
        double sgt = 0.0;
        for (int i = tid; i < n; i += 256) {
            unsigned b = __float_as_uint(cand[i]);
            if (b > tb) sgt += (double)__uint_as_float(b);
        }
        __syncthreads();
        // simple 256-thread reduce of one double
        {
            int lane = tid & 31, wid = tid >> 5;
#pragma unroll
            for (int o = 16; o; o >>= 1) sgt += __shfl_down_sync(0xffffffffu, sgt, o);
            if (lane == 0) sred[wid] = sgt;
            __syncthreads();
            if (wid == 0) {
                double r = (lane < 8) ? sred[lane] : 0.0;
#pragma unroll
                for (int o = 4; o; o >>= 1) r += __shfl_down_sync(0xffffffffu, r, o);
                sgt = r;
            }
        }
        if (tid == 0)
            s_negrow[row] = sgt + (double)krem * (double)__uint_as_float(tb);
        __syncthreads();
    }

    // final combine
    if (tid == 0) {
        double tp = 0.0, ns = 0.0;
#pragma unroll
        for (int r = 0; r < BB; r++) {
            tp += (double)g_numpos[r*PADW];
            ns += s_negrow[r];
        }
        out[0] = (float)(20.0 * g_locsum / tp);
        out[1] = (float)((g_posce + ns) / tp);
        g_locsum = 0.0;
        g_posce  = 0.0;
    }
    __syncthreads();

    // reset per-row state for next graph replay
    if (tid < BB) {
        int row = tid;
        g_cnt[row*PADW]    = 0u;
        g_numpos[row*PADW] = 0;
        g_rowneg[row]      = 0.0;
    }
}

// ---------------- launch -----------------------------------------------------
extern "C" void kernel_launch(void* const* d_in, const int* in_sizes, int n_in,
                              void* d_out, int out_size) {
    const float* locp = (const float*)d_in[0];
    const float* loct = (const float*)d_in[1];
    const float* cls  = (const float*)d_in[2];
    const int*   tgt  = (const int*)d_in[3];
    float* out = (float*)d_out;

    main_k<<<MAIN_BLOCKS, NTHR>>>(locp, loct, cls, tgt);
    select_k<<<1, 256>>>(out);
}

// round 12
// speedup vs baseline: 1.7595x; 1.7595x over previous
#include <cuda_runtime.h>
#include <stdint.h>

#define BB 32
#define AA 65536
#define CC 21
#define NANCH (BB*AA)
#define MAIN_BLOCKS (NANCH/256)
#define CNT_STRIDE 32            // pad per-row counters to separate cache lines

// ---------------- scratch (device globals; no allocation allowed) ----------
__device__ float        g_cand[NANCH];        // compacted nonzero neg CEs per row
__device__ unsigned int g_cnt[BB*CNT_STRIDE]; // per-row nonzero count (padded)
__device__ int          g_numpos[BB];
__device__ double       g_locsum;
__device__ double       g_posce;
__device__ double       g_negsum;
__device__ int          g_tp;                 // total positives across batch
__device__ unsigned int g_done;

// ---------------- helpers ---------------------------------------------------
// Reduce two doubles at once across a 256-thread block. Results valid on tid 0.
__device__ __forceinline__ void blockReduce2(double& x, double& y, double2* sred) {
    int lane = threadIdx.x & 31, wid = threadIdx.x >> 5;
#pragma unroll
    for (int o = 16; o; o >>= 1) {
        x += __shfl_down_sync(0xffffffffu, x, o);
        y += __shfl_down_sync(0xffffffffu, y, o);
    }
    if (lane == 0) sred[wid] = make_double2(x, y);
    __syncthreads();
    if (wid == 0) {
        double2 r = (lane < 8) ? sred[lane] : make_double2(0.0, 0.0);
        double a = r.x, b = r.y;
#pragma unroll
        for (int o = 4; o; o >>= 1) {
            a += __shfl_down_sync(0xffffffffu, a, o);
            b += __shfl_down_sync(0xffffffffu, b, o);
        }
        x = a; y = b;
    }
}

struct DigitSmem {
    unsigned sS[256];
    unsigned sc[256];
    unsigned swm[8];
    unsigned sdig;
};

// Block-parallel (256 threads) digit finder over a 256-bin shared histogram.
__device__ __forceinline__ unsigned find_digit(const unsigned* __restrict__ hist,
                                               long long& krem, DigitSmem* ds) {
    const int tid = threadIdx.x, lane = tid & 31, w = tid >> 5;
    unsigned c = hist[tid];
    unsigned S = c;
#pragma unroll
    for (int off = 1; off < 32; off <<= 1) {
        unsigned t = __shfl_down_sync(0xffffffffu, S, off);
        if (lane + off < 32) S += t;
    }
    if (lane == 0) ds->swm[w] = S;
    __syncthreads();
    unsigned add = 0;
#pragma unroll
    for (int ww = 0; ww < 8; ww++) if (ww > w) add += ds->swm[ww];
    S += add;
    ds->sS[tid] = S;
    ds->sc[tid] = c;
    __syncthreads();
    bool p = ((long long)S >= krem);
    unsigned bal = __ballot_sync(0xffffffffu, p);
    __syncthreads();
    if (lane == 0) ds->swm[w] = bal;
    __syncthreads();
    if (tid == 0) {
        int dig = 0;
#pragma unroll
        for (int ww = 7; ww >= 0; --ww) {
            if (ds->swm[ww]) { dig = ww * 32 + (31 - __clz(ds->swm[ww])); break; }
        }
        ds->sdig = (unsigned)dig;
    }
    __syncthreads();
    unsigned d = ds->sdig;
    krem -= (long long)ds->sS[d] - (long long)ds->sc[d];
    return d;
}

// ---------------- main kernel ------------------------------------------------
__global__ void __launch_bounds__(256) main_k(const float* __restrict__ locp,
                                              const float* __restrict__ loct,
                                              const float* __restrict__ cls,
                                              const int* __restrict__ tgt) {
    __shared__ float   scls[256*CC];
    __shared__ double2 sred[8];

    const int tid    = threadIdx.x;
    const int lane   = tid & 31;
    const int anchor = blockIdx.x * 256 + tid;
    const int row    = anchor >> 16;          // uniform per block

    // stage cls tile (coalesced float4)
    {
        const float4* src = reinterpret_cast<const float4*>(cls) + (size_t)blockIdx.x * (256*CC/4);
        float4*       dst = reinterpret_cast<float4*>(scls);
#pragma unroll
        for (int i = 0; i < 6; i++) {
            int idx = tid + i * 256;
            if (idx < 256*CC/4) dst[idx] = src[idx];
        }
    }
    __syncthreads();

    int  t   = tgt[anchor];
    bool pos = (t > 0);

    // logsumexp over 21 classes (stride-21 LDS is bank-conflict-free)
    float v[CC];
#pragma unroll
    for (int c = 0; c < CC; c++) v[c] = scls[tid*CC + c];
    float m = v[0];
#pragma unroll
    for (int c = 1; c < CC; c++) m = fmaxf(m, v[c]);
    float s = 0.f;
#pragma unroll
    for (int c = 0; c < CC; c++) s += __expf(v[c] - m);

    int tc = t; tc = tc < 0 ? 0 : (tc > CC-1 ? CC-1 : tc);
    float picked = scls[tid*CC + tc];
    float ce     = (t == -1) ? 0.f : (m + __logf(s) - picked);
    float negc   = pos ? 0.f : ce;

    // compact nonzero negatives (warp-aggregated)
    {
        unsigned bits = __float_as_uint(negc);
        unsigned mkz  = __ballot_sync(0xffffffffu, bits != 0u);
        if (mkz) {
            int leader = __ffs(mkz) - 1;
            unsigned base = 0;
            if (lane == leader) base = atomicAdd(&g_cnt[row*CNT_STRIDE], (unsigned)__popc(mkz));
            base = __shfl_sync(0xffffffffu, base, leader);
            if (bits != 0u) {
                unsigned off = (unsigned)__popc(mkz & ((1u << lane) - 1u));
                g_cand[(size_t)row*AA + base + off] = negc;
            }
        }
    }

    // smooth-L1 (unconditional loads; masked result)
    float4 p = reinterpret_cast<const float4*>(locp)[anchor];
    float4 q = reinterpret_cast<const float4*>(loct)[anchor];
    float d0 = p.x-q.x, d1 = p.y-q.y, d2 = p.z-q.z, d3 = p.w-q.w;
    float a0 = fabsf(d0), a1 = fabsf(d1), a2 = fabsf(d2), a3 = fabsf(d3);
    float lsum = (a0 < 1.f ? 0.5f*d0*d0 : a0-0.5f)
               + (a1 < 1.f ? 0.5f*d1*d1 : a1-0.5f)
               + (a2 < 1.f ? 0.5f*d2*d2 : a2-0.5f)
               + (a3 < 1.f ? 0.5f*d3*d3 : a3-0.5f);
    if (!pos) lsum = 0.f;

    int npos = __syncthreads_count(pos ? 1 : 0);

    double bl = (double)lsum;
    double bp = pos ? (double)ce : 0.0;
    blockReduce2(bl, bp, sred);

    if (tid == 0) {
        atomicAdd(&g_locsum, bl);
        atomicAdd(&g_posce,  bp);
        atomicAdd(&g_numpos[row], npos);
    }
}

// ---------------- tiny per-row select on compacted list ----------------------
__global__ void __launch_bounds__(256) select_k(float* __restrict__ out) {
    __shared__ DigitSmem ds;
    __shared__ unsigned  shist[256];
    __shared__ double2   sred[8];
    __shared__ int       s_last;

    const int row = blockIdx.x;
    const int tid = threadIdx.x;

    const int n    = (int)g_cnt[row*CNT_STRIDE];
    const int npos = g_numpos[row];
    long long k = 3LL * (long long)npos;
    if (k < 1) k = 1;
    if (k > AA-1) k = AA-1;

    const float* cand = g_cand + (size_t)row*AA;

    // pass 1: total sum + level-0 histogram
    shist[tid] = 0u;
    __syncthreads();
    double tot = 0.0;
    for (int i = tid; i < n; i += 256) {
        float f = cand[i];
        tot += (double)f;
        atomicAdd(&shist[__float_as_uint(f) >> 24], 1u);
    }
    __syncthreads();
    {
        double dummy = 0.0;
        blockReduce2(tot, dummy, sred);   // tot now valid on tid 0
    }
    __syncthreads();

    double negrow;
    if (k >= (long long)n) {
        negrow = tot;                     // all nonzeros selected; ties are zeros (tid 0 valid)
    } else {
        long long krem = k;
        unsigned pfx = find_digit(shist, krem, &ds);
        // levels 1..3
#pragma unroll
        for (int shift = 16; shift >= 0; shift -= 8) {
            __syncthreads();
            shist[tid] = 0u;
            __syncthreads();
            for (int i = tid; i < n; i += 256) {
                unsigned b = __float_as_uint(cand[i]);
                if ((b >> (shift + 8)) == pfx)
                    atomicAdd(&shist[(b >> shift) & 255u], 1u);
            }
            __syncthreads();
            pfx = (pfx << 8) | find_digit(shist, krem, &ds);
        }
        const unsigned tb = pfx;
        double sgt = 0.0, dummy = 0.0;
        for (int i = tid; i < n; i += 256) {
            unsigned b = __float_as_uint(cand[i]);
            if (b > tb) sgt += (double)__uint_as_float(b);
        }
        blockReduce2(sgt, dummy, sred);
        negrow = sgt + (double)krem * (double)__uint_as_float(tb);
    }

    // per-row state reset for next graph replay
    if (tid == 0) {
        g_cnt[row*CNT_STRIDE] = 0u;
        g_numpos[row] = 0;
        atomicAdd(&g_negsum, negrow);
        atomicAdd(&g_tp, npos);
        __threadfence();
        unsigned ticket = atomicAdd(&g_done, 1u);
        s_last = (ticket == BB - 1) ? 1 : 0;
    }
    __syncthreads();

    if (s_last && tid == 0) {
        __threadfence();
        double tp = (double)g_tp;
        out[0] = (float)(20.0 * g_locsum / tp);
        out[1] = (float)((g_posce + g_negsum) / tp);
        g_locsum = 0.0;
        g_posce  = 0.0;
        g_negsum = 0.0;
        g_tp     = 0;
        __threadfence();
        g_done   = 0u;
    }
}

// ---------------- launch -----------------------------------------------------
extern "C" void kernel_launch(void* const* d_in, const int* in_sizes, int n_in,
                              void* d_out, int out_size) {
    const float* locp = (const float*)d_in[0];
    const float* loct = (const float*)d_in[1];
    const float* cls  = (const float*)d_in[2];
    const int*   tgt  = (const int*)d_in[3];
    float* out = (float*)d_out;

    main_k<<<MAIN_BLOCKS, 256>>>(locp, loct, cls, tgt);
    select_k<<<BB, 256>>>(out);
}